// round 2
// baseline (speedup 1.0000x reference)
#include <cuda_runtime.h>
#include <cstdint>

// Fully fused Precoding-GNN: one sample per 2-CTA cluster, hidden state
// resident in SMEM across all 5 layers. f32x2 packed-FMA edge GEMMs.
// BS=1024, M=64, K=32, D=32. Each CTA owns 32 antennas -> 1024 edges.
// h layout: h[d][e], e = m_loc*32 + k (pitch 1024 floats).

#define NT 512
#define NW 16

typedef unsigned long long ull;

struct SM {
  float h[32 * 1024];   // 131072 B hidden state [d][e]
  float xs[2 * 1024];   //   8192 B layer-1 input [c][e]
  float wsT[1024];      //   4096 B Ws^T staged: wsT[d*DOUT+h]
  float wm[1024];       //   4096 B Wm staged (row-major as in gmem)
  float wk[1024];       //   4096 B Wk staged
  float mm[32 * 34];    //   4352 B msg_m[m][d]   (pitch 34)
  float mkp[32 * 34];   //   4352 B msg_k partial [k][d]
  float mkc[32 * 34];   //   4352 B msg_k combined [k][d]
  float bm[32 * 34];    //   4352 B Wm@msg_m  [m][h]
  float bk[32 * 34];    //   4352 B Wk@msg_k  [k][h]
  float red[NW];
  float powslot;
  float alpha_s;
};

struct Params {
  const float* x;
  const float* w[15];
  float* out;
};

extern __shared__ __align__(16) char smem_raw[];

__device__ __forceinline__ uint32_t s2u(const void* p) {
  uint32_t a;
  asm("{ .reg .u64 t; cvta.to.shared.u64 t, %1; cvt.u32.u64 %0, t; }"
      : "=r"(a) : "l"(p));
  return a;
}
__device__ __forceinline__ float peer_ldf(const float* p, uint32_t peer) {
  uint32_t ra;
  asm("mapa.shared::cluster.u32 %0, %1, %2;" : "=r"(ra) : "r"(s2u(p)), "r"(peer));
  float v;
  asm volatile("ld.shared::cluster.f32 %0, [%1];" : "=f"(v) : "r"(ra));
  return v;
}
__device__ __forceinline__ void csync() {
  asm volatile("barrier.cluster.arrive.aligned;" ::: "memory");
  asm volatile("barrier.cluster.wait.aligned;" ::: "memory");
}
__device__ __forceinline__ ull pk2(float x, float y) {
  ull r; asm("mov.b64 %0,{%1,%2};" : "=l"(r) : "f"(x), "f"(y)); return r;
}
__device__ __forceinline__ void upk2(ull v, float& x, float& y) {
  asm("mov.b64 {%0,%1},%2;" : "=f"(x), "=f"(y) : "l"(v));
}
__device__ __forceinline__ void fma2(ull& d, ull a, ull b) {
  asm("fma.rn.f32x2 %0,%1,%2,%0;" : "+l"(d) : "l"(a), "l"(b));
}

// msg_m[m][d] = sum_k src[d][m*32+k]  (contiguous loads, 8-lane shfl tree)
// mkp[k][d]  = sum_{m_loc} src[d][m*32+k]  (contiguous-lane, serial over m)
template <int DIN>
__device__ __forceinline__ void msgs(SM* s, const float* src, int lane, int wid) {
  for (int r = wid; r < DIN * 8; r += NW) {
    int d = r >> 3, g = r & 7;  // g: group of 4 antennas (128 floats)
    float4 v = *(const float4*)(src + d * 1024 + g * 128 + lane * 4);
    float t = v.x + v.y + v.z + v.w;
    t += __shfl_xor_sync(0xffffffffu, t, 1);
    t += __shfl_xor_sync(0xffffffffu, t, 2);
    t += __shfl_xor_sync(0xffffffffu, t, 4);
    if ((lane & 7) == 0) s->mm[(g * 4 + (lane >> 3)) * 34 + d] = t;
  }
  for (int d = wid; d < DIN; d += NW) {
    float t = 0.f;
#pragma unroll
    for (int m2 = 0; m2 < 32; m2++) t += src[d * 1024 + m2 * 32 + lane];
    s->mkp[lane * 34 + d] = t;
  }
}

template <int DIN>
__device__ __forceinline__ void combine_mk(SM* s, int tid, uint32_t peer) {
  for (int i = tid; i < 32 * DIN; i += NT) {
    int k = i / DIN, d = i % DIN;
    int idx = k * 34 + d;
    s->mkc[idx] = s->mkp[idx] + peer_ldf(s->mkp + idx, peer);
  }
}

// One GNN layer with DOUT=32. src = xs (layer1) or h (layers 2-4), dest = h.
// In-place safe: each thread writes only its own 2 edges, which no other
// thread reads after the pre-cluster.sync msg phase.
template <int DIN, bool RELU>
__device__ __forceinline__ void layer32(SM* s, const float* src,
                                        const float* gWs, const float* gWm,
                                        const float* gWk, int tid, int lane,
                                        int wid, uint32_t peer) {
  // stage weights (Ws transposed so (h,h+1) pairs are contiguous per d)
  for (int i = tid; i < DIN * 32; i += NT) {
    int d = i >> 5, hh = i & 31;
    s->wsT[d * 32 + hh] = gWs[hh * DIN + d];
  }
  for (int i = tid; i < 32 * DIN; i += NT) {
    s->wm[i] = gWm[i];
    s->wk[i] = gWk[i];
  }
  msgs<DIN>(s, src, lane, wid);
  csync();  // partials + staged weights + mm visible everywhere
  combine_mk<DIN>(s, tid, peer);
  __syncthreads();
  // bias GEMMs: bm[m][h] = Wm@msg_m, bk[k][h] = Wk@msg_k
  for (int p = tid; p < 1024; p += NT) {
    int hh = p >> 5, mk = p & 31;  // lanes vary mk -> conflict-free; wm broadcast
    float tb = 0.f, tk = 0.f;
#pragma unroll
    for (int d = 0; d < DIN; d++) {
      tb += s->wm[hh * DIN + d] * s->mm[mk * 34 + d];
      tk += s->wk[hh * DIN + d] * s->mkc[mk * 34 + d];
    }
    s->bm[mk * 34 + hh] = tb;
    s->bk[mk * 34 + hh] = tk;
  }
  __syncthreads();
  // edge GEMM: 2 edges/thread, 16 f32x2 accumulators per edge (paired dout)
  {
    const int e0 = 2 * tid, m = e0 >> 5, k0 = e0 & 31;
    ull a0[16], a1[16];
#pragma unroll
    for (int j = 0; j < 16; j++) {
      float2 bmv = *(const float2*)(s->bm + m * 34 + 2 * j);
      float2 b0v = *(const float2*)(s->bk + k0 * 34 + 2 * j);
      float2 b1v = *(const float2*)(s->bk + (k0 + 1) * 34 + 2 * j);
      a0[j] = pk2(bmv.x + b0v.x, bmv.y + b0v.y);
      a1[j] = pk2(bmv.x + b1v.x, bmv.y + b1v.y);
    }
#pragma unroll 4
    for (int d = 0; d < DIN; d++) {
      float2 hv = *(const float2*)(src + d * 1024 + e0);
      ull H0 = pk2(hv.x, hv.x), H1 = pk2(hv.y, hv.y);
#pragma unroll
      for (int j = 0; j < 16; j++) {
        ull w = *(const ull*)(s->wsT + d * 32 + 2 * j);  // warp-uniform -> bcast
        fma2(a0[j], H0, w);
        fma2(a1[j], H1, w);
      }
    }
#pragma unroll
    for (int j = 0; j < 16; j++) {
      float x0, x1, y0, y1;
      upk2(a0[j], x0, x1);
      upk2(a1[j], y0, y1);
      if (RELU) {
        x0 = fmaxf(x0, 0.f); x1 = fmaxf(x1, 0.f);
        y0 = fmaxf(y0, 0.f); y1 = fmaxf(y1, 0.f);
      }
      *(float2*)(s->h + (2 * j) * 1024 + e0) = make_float2(x0, y0);
      *(float2*)(s->h + (2 * j + 1) * 1024 + e0) = make_float2(x1, y1);
    }
  }
  csync();  // h visible; mkp safe to overwrite next layer
}

__global__ void __launch_bounds__(NT, 1) __cluster_dims__(2, 1, 1)
gnn_kernel(Params p) {
  SM* s = (SM*)smem_raw;
  const int tid = threadIdx.x, lane = tid & 31, wid = tid >> 5;
  uint32_t rank;
  asm("mov.u32 %0, %%cluster_ctarank;" : "=r"(rank));
  const uint32_t peer = rank ^ 1u;
  const int sample = blockIdx.x >> 1;

  // stage x -> xs[c][e] (one float4 = 2 edges x 2 channels per thread)
  {
    const float* xg = p.x + (size_t)sample * 4096 + (size_t)rank * 2048;
    float4 v = *(const float4*)(xg + 4 * tid);
    int e0 = 2 * tid;
    s->xs[e0] = v.x; s->xs[e0 + 1] = v.z;
    s->xs[1024 + e0] = v.y; s->xs[1024 + e0 + 1] = v.w;
  }
  __syncthreads();

  layer32<2, true>(s, s->xs, p.w[0], p.w[1], p.w[2], tid, lane, wid, peer);
  layer32<32, true>(s, s->h, p.w[3], p.w[4], p.w[5], tid, lane, wid, peer);
  layer32<32, true>(s, s->h, p.w[6], p.w[7], p.w[8], tid, lane, wid, peer);
  layer32<32, true>(s, s->h, p.w[9], p.w[10], p.w[11], tid, lane, wid, peer);

  // ---- layer 5 (DIN=32, DOUT=2, no relu) + power norm + store ----
  {
    const float* gWs = p.w[12];
    const float* gWm = p.w[13];
    const float* gWk = p.w[14];
    for (int i = tid; i < 64; i += NT) {
      int d = i >> 1, hh = i & 1;
      s->wsT[d * 2 + hh] = gWs[hh * 32 + d];
    }
    for (int i = tid; i < 64; i += NT) {
      s->wm[i] = gWm[i];
      s->wk[i] = gWk[i];
    }
    msgs<32>(s, s->h, lane, wid);
    csync();
    combine_mk<32>(s, tid, peer);
    __syncthreads();
    for (int pp = tid; pp < 64; pp += NT) {
      int hh = pp >> 5, mk = pp & 31;
      float tb = 0.f, tk = 0.f;
#pragma unroll
      for (int d = 0; d < 32; d++) {
        tb += s->wm[hh * 32 + d] * s->mm[mk * 34 + d];
        tk += s->wk[hh * 32 + d] * s->mkc[mk * 34 + d];
      }
      s->bm[mk * 34 + hh] = tb;
      s->bk[mk * 34 + hh] = tk;
    }
    __syncthreads();

    const int e0 = 2 * tid, m = e0 >> 5, k0 = e0 & 31;
    float2 bmv = *(const float2*)(s->bm + m * 34);
    float2 b0v = *(const float2*)(s->bk + k0 * 34);
    float2 b1v = *(const float2*)(s->bk + (k0 + 1) * 34);
    ull a0 = pk2(bmv.x + b0v.x, bmv.y + b0v.y);
    ull a1 = pk2(bmv.x + b1v.x, bmv.y + b1v.y);
#pragma unroll 8
    for (int d = 0; d < 32; d++) {
      float2 hv = *(const float2*)(s->h + d * 1024 + e0);
      ull w = *(const ull*)(s->wsT + d * 2);
      fma2(a0, pk2(hv.x, hv.x), w);
      fma2(a1, pk2(hv.y, hv.y), w);
    }
    float x0, x1, y0, y1;
    upk2(a0, x0, x1);
    upk2(a1, y0, y1);

    // power = sum over whole sample of z^2
    float pl = x0 * x0 + x1 * x1 + y0 * y0 + y1 * y1;
    pl += __shfl_xor_sync(0xffffffffu, pl, 1);
    pl += __shfl_xor_sync(0xffffffffu, pl, 2);
    pl += __shfl_xor_sync(0xffffffffu, pl, 4);
    pl += __shfl_xor_sync(0xffffffffu, pl, 8);
    pl += __shfl_xor_sync(0xffffffffu, pl, 16);
    if (lane == 0) s->red[wid] = pl;
    __syncthreads();
    if (tid == 0) {
      float t = 0.f;
#pragma unroll
      for (int w2 = 0; w2 < NW; w2++) t += s->red[w2];
      s->powslot = t;
    }
    csync();  // both CTAs' powslot ready
    if (tid == 0)
      s->alpha_s = rsqrtf(s->powslot + peer_ldf(&s->powslot, peer));  // PT = 1
    csync();  // alpha broadcast; also: no DSMEM reads after this point
    float al = s->alpha_s;

    float4 o = make_float4(al * x0, al * x1, al * y0, al * y1);
    *(float4*)(p.out + (size_t)sample * 4096 + (size_t)rank * 2048 + 4 * tid) = o;
  }
}

extern "C" void kernel_launch(void* const* d_in, const int* in_sizes, int n_in,
                              void* d_out, int out_size) {
  Params p;
  p.x = (const float*)d_in[0];
  for (int i = 0; i < 15; i++) p.w[i] = (const float*)d_in[1 + i];
  p.out = (float*)d_out;
  cudaFuncSetAttribute(gnn_kernel, cudaFuncAttributeMaxDynamicSharedMemorySize,
                       (int)sizeof(SM));
  gnn_kernel<<<2048, NT, sizeof(SM)>>>(p);
}

// round 3
// speedup vs baseline: 1.0394x; 1.0394x over previous
#include <cuda_runtime.h>
#include <cstdint>

// Fully fused Precoding-GNN: one sample per 2-CTA cluster, hidden state
// resident in SMEM across all 5 layers. f32x2 packed-FMA edge GEMMs with
// LDS.128 weight broadcasts, double-buffered msg_k partials (1 cluster.sync
// per layer), single code instance for the three 32->32 layers.
// BS=1024, M=64, K=32, D=32. Each CTA owns 32 antennas -> 1024 edges.
// h layout: h[d][e], e = m_loc*32 + k (pitch 1024 floats).

#define NT 512
#define NW 16

typedef unsigned long long ull;

struct SM {
  float h[32 * 1024];      // 131072 B hidden state [d][e]
  float xs[2 * 1024];      //   8192 B layer-1 input [c][e]
  float wsT[1024];         //   4096 B Ws^T staged: wsT[d*32+h] (16B aligned)
  float wm[1024];          //   4096 B Wm staged (row-major as in gmem)
  float wk[1024];          //   4096 B Wk staged
  float mm[32 * 34];       //   4352 B msg_m[m][d]   (pitch 34)
  float mkp[2][32 * 34];   //   8704 B msg_k partial [k][d], double buffered
  float mkc[32 * 34];      //   4352 B msg_k combined [k][d]
  float bm[32 * 34];       //   4352 B Wm@msg_m  [m][h]
  float bk[32 * 34];       //   4352 B Wk@msg_k  [k][h]
  float red[NW];
  float powslot;
};

struct Params {
  const float* x;
  const float* w[15];
  float* out;
};

extern __shared__ __align__(16) char smem_raw[];

__device__ __forceinline__ uint32_t s2u(const void* p) {
  uint32_t a;
  asm("{ .reg .u64 t; cvta.to.shared.u64 t, %1; cvt.u32.u64 %0, t; }"
      : "=r"(a) : "l"(p));
  return a;
}
__device__ __forceinline__ float peer_ldf(const float* p, uint32_t peer) {
  uint32_t ra;
  asm("mapa.shared::cluster.u32 %0, %1, %2;" : "=r"(ra) : "r"(s2u(p)), "r"(peer));
  float v;
  asm volatile("ld.shared::cluster.f32 %0, [%1];" : "=f"(v) : "r"(ra));
  return v;
}
__device__ __forceinline__ void csync() {
  asm volatile("barrier.cluster.arrive.aligned;" ::: "memory");
  asm volatile("barrier.cluster.wait.aligned;" ::: "memory");
}
__device__ __forceinline__ ull pk2(float x, float y) {
  ull r; asm("mov.b64 %0,{%1,%2};" : "=l"(r) : "f"(x), "f"(y)); return r;
}
__device__ __forceinline__ void upk2(ull v, float& x, float& y) {
  asm("mov.b64 {%0,%1},%2;" : "=f"(x), "=f"(y) : "l"(v));
}
__device__ __forceinline__ void fma2(ull& d, ull a, ull b) {
  asm("fma.rn.f32x2 %0,%1,%2,%0;" : "+l"(d) : "l"(a), "l"(b));
}

// msg_m[m][d] = sum_k src[d][m*32+k]  (contiguous float4 loads, shfl tree)
// mkp[k][d]  = sum_{m_loc} src[d][m*32+k]  (contiguous-lane, serial over m)
template <int DIN>
__device__ __forceinline__ void msgs(SM* s, const float* src, float* mkp,
                                     int lane, int wid) {
  for (int r = wid; r < DIN * 8; r += NW) {
    int d = r >> 3, g = r & 7;  // g: group of 4 antennas (128 floats)
    float4 v = *(const float4*)(src + d * 1024 + g * 128 + lane * 4);
    float t = v.x + v.y + v.z + v.w;
    t += __shfl_xor_sync(0xffffffffu, t, 1);
    t += __shfl_xor_sync(0xffffffffu, t, 2);
    t += __shfl_xor_sync(0xffffffffu, t, 4);
    if ((lane & 7) == 0) s->mm[(g * 4 + (lane >> 3)) * 34 + d] = t;
  }
  for (int d = wid; d < DIN; d += NW) {
    float t = 0.f;
#pragma unroll
    for (int m2 = 0; m2 < 32; m2++) t += src[d * 1024 + m2 * 32 + lane];
    mkp[lane * 34 + d] = t;
  }
}

template <int DIN>
__device__ __forceinline__ void combine_mk(SM* s, const float* mkp, int tid,
                                           uint32_t peer) {
  for (int i = tid; i < 32 * DIN; i += NT) {
    int k = i / DIN, d = i % DIN;
    int idx = k * 34 + d;
    s->mkc[idx] = mkp[idx] + peer_ldf(mkp + idx, peer);
  }
}

// One GNN layer with DOUT=32. src = xs (layer1) or h (layers 2-4), dest = h.
// In-place safe: each thread reads/writes only its own 2 edge columns.
template <int DIN, bool RELU>
__device__ __forceinline__ void layer32(SM* s, const float* src,
                                        const float* gWs, const float* gWm,
                                        const float* gWk, int par, int tid,
                                        int lane, int wid, uint32_t peer) {
  float* mkp = s->mkp[par];
  // stage weights (Ws transposed so (h..h+3) quads are contiguous per d)
  for (int i = tid; i < DIN * 32; i += NT) {
    int d = i >> 5, hh = i & 31;
    s->wsT[d * 32 + hh] = gWs[hh * DIN + d];
  }
  for (int i = tid; i < 32 * DIN; i += NT) {
    s->wm[i] = gWm[i];
    s->wk[i] = gWk[i];
  }
  msgs<DIN>(s, src, mkp, lane, wid);
  csync();  // both CTAs' mkp[par] written (also orders local staging/mm)
  combine_mk<DIN>(s, mkp, tid, peer);
  __syncthreads();
  // bias GEMMs: bm[m][h] = Wm@msg_m, bk[k][h] = Wk@msg_k
  for (int p = tid; p < 1024; p += NT) {
    int hh = p >> 5, mk = p & 31;  // hh warp-uniform -> wm/wk broadcast
    float tb = 0.f, tk = 0.f;
#pragma unroll
    for (int d = 0; d < DIN; d++) {
      tb += s->wm[hh * DIN + d] * s->mm[mk * 34 + d];
      tk += s->wk[hh * DIN + d] * s->mkc[mk * 34 + d];
    }
    s->bm[mk * 34 + hh] = tb;
    s->bk[mk * 34 + hh] = tk;
  }
  __syncthreads();
  // edge GEMM: 2 edges/thread, 16 f32x2 accumulators per edge (paired dout)
  {
    const int e0 = 2 * tid, m = e0 >> 5, k0 = e0 & 31;
    ull a0[16], a1[16];
#pragma unroll
    for (int j = 0; j < 16; j++) {
      float2 bmv = *(const float2*)(s->bm + m * 34 + 2 * j);
      float2 b0v = *(const float2*)(s->bk + k0 * 34 + 2 * j);
      float2 b1v = *(const float2*)(s->bk + (k0 + 1) * 34 + 2 * j);
      a0[j] = pk2(bmv.x + b0v.x, bmv.y + b0v.y);
      a1[j] = pk2(bmv.x + b1v.x, bmv.y + b1v.y);
    }
    const ulonglong2* wrow = (const ulonglong2*)s->wsT;  // 2 f32x2 per elem
#pragma unroll 4
    for (int d = 0; d < DIN; d++) {
      float2 hv = *(const float2*)(src + d * 1024 + e0);
      ull H0 = pk2(hv.x, hv.x), H1 = pk2(hv.y, hv.y);
#pragma unroll
      for (int q = 0; q < 8; q++) {
        ulonglong2 w = wrow[d * 8 + q];  // LDS.128 broadcast, zero repack
        fma2(a0[2 * q], H0, w.x);
        fma2(a0[2 * q + 1], H0, w.y);
        fma2(a1[2 * q], H1, w.x);
        fma2(a1[2 * q + 1], H1, w.y);
      }
    }
#pragma unroll
    for (int j = 0; j < 16; j++) {
      float x0, x1, y0, y1;
      upk2(a0[j], x0, x1);
      upk2(a1[j], y0, y1);
      if (RELU) {
        x0 = fmaxf(x0, 0.f); x1 = fmaxf(x1, 0.f);
        y0 = fmaxf(y0, 0.f); y1 = fmaxf(y1, 0.f);
      }
      *(float2*)(s->h + (2 * j) * 1024 + e0) = make_float2(x0, y0);
      *(float2*)(s->h + (2 * j + 1) * 1024 + e0) = make_float2(x1, y1);
    }
  }
  __syncthreads();  // h ready for next layer's local reads; wsT reusable
}

__global__ void __launch_bounds__(NT, 1) __cluster_dims__(2, 1, 1)
gnn_kernel(Params p) {
  SM* s = (SM*)smem_raw;
  const int tid = threadIdx.x, lane = tid & 31, wid = tid >> 5;
  uint32_t rank;
  asm("mov.u32 %0, %%cluster_ctarank;" : "=r"(rank));
  const uint32_t peer = rank ^ 1u;
  const int sample = blockIdx.x >> 1;

  // stage x -> xs[c][e] (one float4 = 2 edges x 2 channels per thread)
  {
    const float* xg = p.x + (size_t)sample * 4096 + (size_t)rank * 2048;
    float4 v = *(const float4*)(xg + 4 * tid);
    int e0 = 2 * tid;
    s->xs[e0] = v.x; s->xs[e0 + 1] = v.z;
    s->xs[1024 + e0] = v.y; s->xs[1024 + e0 + 1] = v.w;
  }
  __syncthreads();

  // layer parities: L1:0 L2:1 L3:0 L4:1 L5:0  (overwrite distance 2 => safe)
  layer32<2, true>(s, s->xs, p.w[0], p.w[1], p.w[2], 0, tid, lane, wid, peer);
  for (int l = 1; l < 4; ++l)
    layer32<32, true>(s, s->h, p.w[3 * l], p.w[3 * l + 1], p.w[3 * l + 2],
                      l & 1, tid, lane, wid, peer);

  // ---- layer 5 (DIN=32, DOUT=2, no relu) + power norm + store ----
  {
    const float* gWs = p.w[12];
    const float* gWm = p.w[13];
    const float* gWk = p.w[14];
    float* mkp = s->mkp[0];
    for (int i = tid; i < 64; i += NT) {
      int d = i >> 1, hh = i & 1;
      s->wsT[d * 2 + hh] = gWs[hh * 32 + d];
    }
    for (int i = tid; i < 64; i += NT) {
      s->wm[i] = gWm[i];
      s->wk[i] = gWk[i];
    }
    msgs<32>(s, s->h, mkp, lane, wid);
    csync();
    combine_mk<32>(s, mkp, tid, peer);
    __syncthreads();
    for (int pp = tid; pp < 64; pp += NT) {
      int hh = pp >> 5, mk = pp & 31;
      float tb = 0.f, tk = 0.f;
#pragma unroll
      for (int d = 0; d < 32; d++) {
        tb += s->wm[hh * 32 + d] * s->mm[mk * 34 + d];
        tk += s->wk[hh * 32 + d] * s->mkc[mk * 34 + d];
      }
      s->bm[mk * 34 + hh] = tb;
      s->bk[mk * 34 + hh] = tk;
    }
    __syncthreads();

    const int e0 = 2 * tid, m = e0 >> 5, k0 = e0 & 31;
    float2 bmv = *(const float2*)(s->bm + m * 34);
    float2 b0v = *(const float2*)(s->bk + k0 * 34);
    float2 b1v = *(const float2*)(s->bk + (k0 + 1) * 34);
    ull a0 = pk2(bmv.x + b0v.x, bmv.y + b0v.y);
    ull a1 = pk2(bmv.x + b1v.x, bmv.y + b1v.y);
#pragma unroll 8
    for (int d = 0; d < 32; d++) {
      float2 hv = *(const float2*)(s->h + d * 1024 + e0);
      ull w = *(const ull*)(s->wsT + d * 2);
      fma2(a0, pk2(hv.x, hv.x), w);
      fma2(a1, pk2(hv.y, hv.y), w);
    }
    float x0, x1, y0, y1;
    upk2(a0, x0, x1);
    upk2(a1, y0, y1);

    // power = sum over whole sample of z^2
    float pl = x0 * x0 + x1 * x1 + y0 * y0 + y1 * y1;
    pl += __shfl_xor_sync(0xffffffffu, pl, 1);
    pl += __shfl_xor_sync(0xffffffffu, pl, 2);
    pl += __shfl_xor_sync(0xffffffffu, pl, 4);
    pl += __shfl_xor_sync(0xffffffffu, pl, 8);
    pl += __shfl_xor_sync(0xffffffffu, pl, 16);
    if (lane == 0) s->red[wid] = pl;
    __syncthreads();
    if (tid == 0) {
      float t = 0.f;
#pragma unroll
      for (int w2 = 0; w2 < NW; w2++) t += s->red[w2];
      s->powslot = t;
    }
    csync();  // both CTAs' powslot ready
    float al = rsqrtf(s->powslot + peer_ldf(&s->powslot, peer));  // PT = 1

    float4 o = make_float4(al * x0, al * x1, al * y0, al * y1);
    *(float4*)(p.out + (size_t)sample * 4096 + (size_t)rank * 2048 + 4 * tid) = o;
    csync();  // keep our smem alive until peer finished its powslot read
  }
}

extern "C" void kernel_launch(void* const* d_in, const int* in_sizes, int n_in,
                              void* d_out, int out_size) {
  Params p;
  p.x = (const float*)d_in[0];
  for (int i = 0; i < 15; i++) p.w[i] = (const float*)d_in[1 + i];
  p.out = (float*)d_out;
  cudaFuncSetAttribute(gnn_kernel, cudaFuncAttributeMaxDynamicSharedMemorySize,
                       (int)sizeof(SM));
  gnn_kernel<<<2048, NT, sizeof(SM)>>>(p);
}